// round 1
// baseline (speedup 1.0000x reference)
#include <cuda_runtime.h>
#include <math.h>

#define N_TOT 8192
#define B_CUR 4096
#define C_DIM 256
#define KU    288
#define TWO_PI 6.283185307179586f
#define SQA 0.97467943f   // sqrt(0.95)
#define SQP 0.22360680f   // sqrt(0.05)

// Scratch (static device allocs are allowed)
__device__ float g_U[(size_t)N_TOT * KU];   // [sqrt(a)*fhat | sqrt(1-a)*phat], row-major, 288 wide
__device__ float g_thr[N_TOT];              // 15th-largest off-diagonal value per row
__device__ float g_rsd[N_TOT];              // deg^-1/2 per row

// ---------------------------------------------------------------------------
// Kernel 1: build U rows (normalized scaled features + pos enc), copy raw
// features into the node_feats output region.
// One warp per row, 8 warps per block.
// ---------------------------------------------------------------------------
__global__ void __launch_bounds__(256) prep_kernel(
    const float* __restrict__ feats, const float* __restrict__ coords,
    const float* __restrict__ hfeats, const float* __restrict__ hcoords,
    float* __restrict__ out_feats)
{
    int row  = blockIdx.x * 8 + threadIdx.y;
    int lane = threadIdx.x;

    const float* f = (row < B_CUR) ? (feats  + (size_t)row * C_DIM)
                                   : (hfeats + (size_t)(row - B_CUR) * C_DIM);
    const float* c = (row < B_CUR) ? (coords  + (size_t)row * 4)
                                   : (hcoords + (size_t)(row - B_CUR) * 4);

    // ---- feature part: 256 floats, 8 per lane ----
    float4 va = ((const float4*)f)[lane * 2 + 0];
    float4 vb = ((const float4*)f)[lane * 2 + 1];
    float ss = va.x*va.x + va.y*va.y + va.z*va.z + va.w*va.w
             + vb.x*vb.x + vb.y*vb.y + vb.z*vb.z + vb.w*vb.w;
    #pragma unroll
    for (int off = 16; off; off >>= 1) ss += __shfl_xor_sync(0xffffffffu, ss, off);
    float s = SQA / fmaxf(sqrtf(ss), 1e-12f);

    float* urow = g_U + (size_t)row * KU;
    ((float4*)urow)[lane * 2 + 0] = make_float4(va.x*s, va.y*s, va.z*s, va.w*s);
    ((float4*)urow)[lane * 2 + 1] = make_float4(vb.x*s, vb.y*s, vb.z*s, vb.w*s);

    // raw feature copy to output
    float4* of = (float4*)(out_feats + (size_t)row * C_DIM);
    of[lane * 2 + 0] = va;
    of[lane * 2 + 1] = vb;

    // ---- positional encoding: 32 values, 1 per lane ----
    int d      = lane >> 3;        // coord dim 0..3
    int rem    = lane & 7;
    int is_cos = rem >> 2;
    int fr     = rem & 3;          // freq 0..3
    float ang = c[d] * TWO_PI * (float)(1 << fr);
    float sv, cv;
    sincosf(ang, &sv, &cv);
    float pe = is_cos ? cv : sv;
    float ps = pe * pe;
    #pragma unroll
    for (int off = 16; off; off >>= 1) ps += __shfl_xor_sync(0xffffffffu, ps, off);
    urow[256 + lane] = pe * (SQP / fmaxf(sqrtf(ps), 1e-12f));
}

// ---------------------------------------------------------------------------
// Kernel 2: symmetric fp32 GEMM A = w .* (U U^T), dense write to adj.
// Only upper-triangular 128x128 tiles computed; mirror written for bi != bj.
// ---------------------------------------------------------------------------
__global__ void __launch_bounds__(256) gemm_kernel(float* __restrict__ adj)
{
    if (blockIdx.x < blockIdx.y) return;   // upper-triangular tiles only
    const int bi = blockIdx.y;
    const int bj = blockIdx.x;
    const int t  = threadIdx.x;
    const int ty = t >> 4, tx = t & 15;

    __shared__ float As[16][132];
    __shared__ float Bs[16][132];

    float acc[8][8];
    #pragma unroll
    for (int m = 0; m < 8; m++)
        #pragma unroll
        for (int n = 0; n < 8; n++) acc[m][n] = 0.f;

    const float* Abase = g_U + (size_t)bi * 128 * KU;
    const float* Bbase = g_U + (size_t)bj * 128 * KU;

    for (int kt = 0; kt < KU; kt += 16) {
        #pragma unroll
        for (int it = 0; it < 2; it++) {
            int id = t + it * 256;
            int r  = id >> 2, c4 = id & 3;
            float4 xa = *(const float4*)(Abase + (size_t)r * KU + kt + c4 * 4);
            As[c4*4+0][r] = xa.x; As[c4*4+1][r] = xa.y;
            As[c4*4+2][r] = xa.z; As[c4*4+3][r] = xa.w;
            float4 xb = *(const float4*)(Bbase + (size_t)r * KU + kt + c4 * 4);
            Bs[c4*4+0][r] = xb.x; Bs[c4*4+1][r] = xb.y;
            Bs[c4*4+2][r] = xb.z; Bs[c4*4+3][r] = xb.w;
        }
        __syncthreads();
        #pragma unroll
        for (int kk = 0; kk < 16; kk++) {
            float a[8], b[8];
            #pragma unroll
            for (int m = 0; m < 8; m++) a[m] = As[kk][ty * 8 + m];
            #pragma unroll
            for (int n = 0; n < 8; n++) b[n] = Bs[kk][tx * 8 + n];
            #pragma unroll
            for (int m = 0; m < 8; m++)
                #pragma unroll
                for (int n = 0; n < 8; n++)
                    acc[m][n] = fmaf(a[m], b[n], acc[m][n]);
        }
        __syncthreads();
    }

    // cross-block weight is uniform per tile (4096 % 128 == 0)
    const float w = ((bi < 32) != (bj < 32)) ? 0.5f : 1.0f;
    const int gi0 = bi * 128 + ty * 8;
    const int gj0 = bj * 128 + tx * 8;

    #pragma unroll
    for (int m = 0; m < 8; m++) {
        float4 v0 = make_float4(acc[m][0]*w, acc[m][1]*w, acc[m][2]*w, acc[m][3]*w);
        float4 v1 = make_float4(acc[m][4]*w, acc[m][5]*w, acc[m][6]*w, acc[m][7]*w);
        float* p = adj + (size_t)(gi0 + m) * N_TOT + gj0;
        *(float4*)(p)     = v0;
        *(float4*)(p + 4) = v1;
    }
    if (bi != bj) {
        #pragma unroll
        for (int n = 0; n < 8; n++) {
            float4 v0 = make_float4(acc[0][n]*w, acc[1][n]*w, acc[2][n]*w, acc[3][n]*w);
            float4 v1 = make_float4(acc[4][n]*w, acc[5][n]*w, acc[6][n]*w, acc[7][n]*w);
            float* p = adj + (size_t)(gj0 + n) * N_TOT + gi0;
            *(float4*)(p)     = v0;
            *(float4*)(p + 4) = v1;
        }
    }
}

// ---------------------------------------------------------------------------
// Kernel 3: per-row top-15 off-diagonal -> threshold + degree (diag always kept).
// One 256-thread block per row. Per-thread sorted top-16 (registers), then
// head-pointer block-wide 15x max extraction via smem candidates.
// ---------------------------------------------------------------------------
__global__ void __launch_bounds__(256) topk_kernel(const float* __restrict__ adj)
{
    const int i    = blockIdx.x;
    const int t    = threadIdx.x;
    const int lane = t & 31, wid = t >> 5;
    const float4* row4 = (const float4*)(adj + (size_t)i * N_TOT);

    __shared__ float cand[256 * 16];
    __shared__ float s_diag;
    __shared__ float warpv[8];
    __shared__ int   warpa[8];
    __shared__ int   s_garg;

    float top[16];
    #pragma unroll
    for (int q = 0; q < 16; q++) top[q] = -INFINITY;

    for (int it = 0; it < 8; it++) {
        int idx4 = t + it * 256;
        float4 v = row4[idx4];
        int j = idx4 * 4;
        float vals[4] = {v.x, v.y, v.z, v.w};
        #pragma unroll
        for (int c = 0; c < 4; c++) {
            float val = vals[c];
            if (j + c == i) { s_diag = val; val = -INFINITY; }
            if (val > top[15]) {
                top[15] = val;
                #pragma unroll
                for (int q = 15; q > 0; q--) {
                    if (top[q] > top[q-1]) {
                        float tmp = top[q-1]; top[q-1] = top[q]; top[q] = tmp;
                    }
                }
            }
        }
    }
    #pragma unroll
    for (int q = 0; q < 16; q++) cand[t * 16 + q] = top[q];
    __syncthreads();

    int head = 0;
    float sum15 = 0.f, thr = 0.f;   // valid in thread 0
    for (int it = 0; it < 15; it++) {
        float bv = cand[t * 16 + head];
        int   bl = lane;
        #pragma unroll
        for (int off = 16; off; off >>= 1) {
            float ov = __shfl_down_sync(0xffffffffu, bv, off);
            int   ol = __shfl_down_sync(0xffffffffu, bl, off);
            if (ov > bv) { bv = ov; bl = ol; }
        }
        if (lane == 0) { warpv[wid] = bv; warpa[wid] = (wid << 5) | bl; }
        __syncthreads();
        if (t == 0) {
            float g = -INFINITY; int ga = 0;
            #pragma unroll
            for (int w = 0; w < 8; w++)
                if (warpv[w] > g) { g = warpv[w]; ga = warpa[w]; }
            s_garg = ga;
            sum15 += g;
            thr = g;
        }
        __syncthreads();
        if (t == s_garg) head++;
    }

    if (t == 0) {
        float deg = s_diag + sum15;
        deg = fmaxf(deg, 1e-12f);
        g_rsd[i] = 1.0f / sqrtf(deg);
        g_thr[i] = thr;
    }
}

// ---------------------------------------------------------------------------
// Kernel 4: in-place sparsify + symmetric normalize:
// out[i][j] = (j==i || A[i][j] >= thr[i]) ? A[i][j]*rsd[i]*rsd[j] : 0
// ---------------------------------------------------------------------------
__global__ void __launch_bounds__(256) finalize_kernel(float* __restrict__ adj)
{
    size_t idx = (size_t)blockIdx.x * 256 + threadIdx.x;  // float4 index
    int i = (int)(idx >> 11);                  // 2048 float4 per row
    int j = (int)((idx & 2047) << 2);
    float thr = g_thr[i];
    float ri  = g_rsd[i];

    float4* p = (float4*)adj + idx;
    float4 v = *p;
    float s0 = ri * g_rsd[j + 0];
    float s1 = ri * g_rsd[j + 1];
    float s2 = ri * g_rsd[j + 2];
    float s3 = ri * g_rsd[j + 3];
    v.x = ((j + 0 == i) || (v.x >= thr)) ? v.x * s0 : 0.f;
    v.y = ((j + 1 == i) || (v.y >= thr)) ? v.y * s1 : 0.f;
    v.z = ((j + 2 == i) || (v.z >= thr)) ? v.z * s2 : 0.f;
    v.w = ((j + 3 == i) || (v.w >= thr)) ? v.w * s3 : 0.f;
    *p = v;
}

// ---------------------------------------------------------------------------
extern "C" void kernel_launch(void* const* d_in, const int* in_sizes, int n_in,
                              void* d_out, int out_size)
{
    const float* feats   = (const float*)d_in[0];   // [4096, 256]
    const float* coords  = (const float*)d_in[1];   // [4096, 4]
    const float* hfeats  = (const float*)d_in[2];   // [128, 32, 256] -> [4096, 256]
    const float* hcoords = (const float*)d_in[3];   // [128, 32, 4]   -> [4096, 4]

    float* adj       = (float*)d_out;                      // [8192, 8192]
    float* out_feats = adj + (size_t)N_TOT * N_TOT;        // [8192, 256]

    prep_kernel<<<N_TOT / 8, dim3(32, 8)>>>(feats, coords, hfeats, hcoords, out_feats);
    gemm_kernel<<<dim3(64, 64), 256>>>(adj);
    topk_kernel<<<N_TOT, 256>>>(adj);
    finalize_kernel<<<(unsigned)((size_t)N_TOT * N_TOT / 4 / 256), 256>>>(adj);
}

// round 3
// speedup vs baseline: 1.0339x; 1.0339x over previous
#include <cuda_runtime.h>
#include <math.h>
#include <stdint.h>

#define N_TOT 8192
#define B_CUR 4096
#define C_DIM 256
#define KU    288
#define TWO_PI 6.283185307179586f
#define SQA 0.97467943f   // sqrt(0.95)
#define SQP 0.22360680f   // sqrt(0.05)

// Scratch
__device__ float g_U[(size_t)N_TOT * KU];
__device__ float g_thr[N_TOT];
__device__ float g_rsd[N_TOT];

// ---------------------------------------------------------------------------
// Helpers
// ---------------------------------------------------------------------------
__device__ __forceinline__ uint32_t smem_u32(const void* p) {
    uint32_t a;
    asm("{ .reg .u64 t; cvta.to.shared.u64 t, %1; cvt.u32.u64 %0, t; }" : "=r"(a) : "l"(p));
    return a;
}

__device__ __forceinline__ float tf32_trunc(float x) {
    uint32_t u;
    asm("cvt.rna.tf32.f32 %0, %1;" : "=r"(u) : "f"(x));
    return __uint_as_float(u);
}

#define LDSM_X4(r0, r1, r2, r3, addr) \
    asm volatile("ldmatrix.sync.aligned.m8n8.x4.shared.b16 {%0,%1,%2,%3}, [%4];" \
        : "=r"(r0), "=r"(r1), "=r"(r2), "=r"(r3) : "r"(addr))

#define MMA_TF32(d, a, b) \
    asm volatile("mma.sync.aligned.m16n8k8.row.col.f32.tf32.tf32.f32 " \
        "{%0,%1,%2,%3}, {%4,%5,%6,%7}, {%8,%9}, {%0,%1,%2,%3};" \
        : "+f"((d)[0]), "+f"((d)[1]), "+f"((d)[2]), "+f"((d)[3]) \
        : "r"((a)[0]), "r"((a)[1]), "r"((a)[2]), "r"((a)[3]), \
          "r"((b)[0]), "r"((b)[1]))

// ---------------------------------------------------------------------------
// Kernel 1: build U rows; copy raw features to output.
// ---------------------------------------------------------------------------
__global__ void __launch_bounds__(256) prep_kernel(
    const float* __restrict__ feats, const float* __restrict__ coords,
    const float* __restrict__ hfeats, const float* __restrict__ hcoords,
    float* __restrict__ out_feats)
{
    int row  = blockIdx.x * 8 + threadIdx.y;
    int lane = threadIdx.x;

    const float* f = (row < B_CUR) ? (feats  + (size_t)row * C_DIM)
                                   : (hfeats + (size_t)(row - B_CUR) * C_DIM);
    const float* c = (row < B_CUR) ? (coords  + (size_t)row * 4)
                                   : (hcoords + (size_t)(row - B_CUR) * 4);

    float4 va = ((const float4*)f)[lane * 2 + 0];
    float4 vb = ((const float4*)f)[lane * 2 + 1];
    float ss = va.x*va.x + va.y*va.y + va.z*va.z + va.w*va.w
             + vb.x*vb.x + vb.y*vb.y + vb.z*vb.z + vb.w*vb.w;
    #pragma unroll
    for (int off = 16; off; off >>= 1) ss += __shfl_xor_sync(0xffffffffu, ss, off);
    float s = SQA / fmaxf(sqrtf(ss), 1e-12f);

    float* urow = g_U + (size_t)row * KU;
    ((float4*)urow)[lane * 2 + 0] = make_float4(va.x*s, va.y*s, va.z*s, va.w*s);
    ((float4*)urow)[lane * 2 + 1] = make_float4(vb.x*s, vb.y*s, vb.z*s, vb.w*s);

    float4* of = (float4*)(out_feats + (size_t)row * C_DIM);
    of[lane * 2 + 0] = va;
    of[lane * 2 + 1] = vb;

    int d      = lane >> 3;
    int rem    = lane & 7;
    int is_cos = rem >> 2;
    int fr     = rem & 3;
    float ang = c[d] * TWO_PI * (float)(1 << fr);
    float sv, cv;
    sincosf(ang, &sv, &cv);
    float pe = is_cos ? cv : sv;
    float ps = pe * pe;
    #pragma unroll
    for (int off = 16; off; off >>= 1) ps += __shfl_xor_sync(0xffffffffu, ps, off);
    urow[256 + lane] = pe * (SQP / fmaxf(sqrtf(ps), 1e-12f));
}

// ---------------------------------------------------------------------------
// Kernel 2: 3xTF32 GEMM via mma.sync.m16n8k8 (HMMA), A = w .* (U U^T).
// 128x128 CTA tile, 8 warps (2x4), warp tile 64x32. K-chunks of 16 floats,
// double-buffered SMEM + register prefetch. ldmatrix.x4 operand fetch.
// SMEM row stride 20 floats -> conflict-free LDSM, 16B-aligned stores.
// ---------------------------------------------------------------------------
#define KCH     16
#define STR     20
#define MAT_SZ  (128 * STR)            // floats per matrix per stage = 2560
#define STAGE_FLOATS (4 * MAT_SZ)      // Ah|Al|Bh|Bl = 10240 floats = 40KB
#define GEMM_SMEM (2 * STAGE_FLOATS * 4)   // 81920B (>= 128*129*4 for epilogue T)
#define NCHUNK (KU / KCH)              // 18

__global__ void __launch_bounds__(256) gemm_kernel(float* __restrict__ adj)
{
    const int bi = blockIdx.y;
    const int bj = blockIdx.x;
    if (bj < bi) return;

    extern __shared__ float sm[];
    const int t    = threadIdx.x;
    const int lane = t & 31;
    const int wid  = t >> 5;
    const int wm   = wid >> 2;     // 0..1
    const int wn   = wid & 3;      // 0..3

    const float* Abase = g_U + (size_t)bi * 128 * KU;
    const float* Bbase = g_U + (size_t)bj * 128 * KU;

    float acc[4][4][4];
    #pragma unroll
    for (int mi = 0; mi < 4; mi++)
        #pragma unroll
        for (int ni = 0; ni < 4; ni++)
            #pragma unroll
            for (int q = 0; q < 4; q++) acc[mi][ni][q] = 0.f;

    float4 pa[2], pb[2];

    // LDSM per-lane addressing (constant across k-chunks except k8/base)
    const int arow = lane & 15;
    const int acol4 = (lane >> 4) << 2;           // 0 or 4
    const int brow = ((lane & 16) >> 1) + (lane & 7);  // +8 for groups 2,3
    const int bcol4 = (lane & 8) ? 4 : 0;

    const uint32_t smb = smem_u32(sm);

#define LOAD_CHUNK(kb) do { \
    _Pragma("unroll") \
    for (int i = 0; i < 2; i++) { \
        int idx = t + (i << 8); int r = idx >> 2; int c4 = idx & 3; \
        pa[i] = *(const float4*)(Abase + (size_t)r * KU + (kb) + c4 * 4); \
        pb[i] = *(const float4*)(Bbase + (size_t)r * KU + (kb) + c4 * 4); \
    } } while (0)

#define STORE_CHUNK(s) do { \
    float* st = sm + (s) * STAGE_FLOATS; \
    _Pragma("unroll") \
    for (int i = 0; i < 2; i++) { \
        int idx = t + (i << 8); int r = idx >> 2; int c4 = idx & 3; \
        int off = r * STR + c4 * 4; \
        float4 a = pa[i], b = pb[i]; \
        float4 ah = make_float4(tf32_trunc(a.x), tf32_trunc(a.y), tf32_trunc(a.z), tf32_trunc(a.w)); \
        float4 al = make_float4(tf32_trunc(a.x - ah.x), tf32_trunc(a.y - ah.y), \
                                tf32_trunc(a.z - ah.z), tf32_trunc(a.w - ah.w)); \
        float4 bh = make_float4(tf32_trunc(b.x), tf32_trunc(b.y), tf32_trunc(b.z), tf32_trunc(b.w)); \
        float4 bl = make_float4(tf32_trunc(b.x - bh.x), tf32_trunc(b.y - bh.y), \
                                tf32_trunc(b.z - bh.z), tf32_trunc(b.w - bh.w)); \
        *(float4*)(st + off)              = ah; \
        *(float4*)(st + MAT_SZ + off)     = al; \
        *(float4*)(st + 2 * MAT_SZ + off) = bh; \
        *(float4*)(st + 3 * MAT_SZ + off) = bl; \
    } } while (0)

#define COMPUTE_STAGE(s) do { \
    uint32_t base = smb + (uint32_t)((s) * STAGE_FLOATS * 4); \
    _Pragma("unroll") \
    for (int k8 = 0; k8 < KCH; k8 += 8) { \
        uint32_t ah[4][4], al_[4][4], bh2[4][2], bl2[4][2]; \
        _Pragma("unroll") \
        for (int mi = 0; mi < 4; mi++) { \
            uint32_t ad = base + (uint32_t)(((wm * 64 + mi * 16 + arow) * STR + k8 + acol4) * 4); \
            LDSM_X4(ah[mi][0], ah[mi][1], ah[mi][2], ah[mi][3], ad); \
            LDSM_X4(al_[mi][0], al_[mi][1], al_[mi][2], al_[mi][3], ad + MAT_SZ * 4); \
        } \
        _Pragma("unroll") \
        for (int nb = 0; nb < 2; nb++) { \
            uint32_t bd = base + (uint32_t)(2 * MAT_SZ * 4) + \
                (uint32_t)(((wn * 32 + nb * 16 + brow) * STR + k8 + bcol4) * 4); \
            LDSM_X4(bh2[2*nb][0], bh2[2*nb][1], bh2[2*nb+1][0], bh2[2*nb+1][1], bd); \
            LDSM_X4(bl2[2*nb][0], bl2[2*nb][1], bl2[2*nb+1][0], bl2[2*nb+1][1], bd + MAT_SZ * 4); \
        } \
        _Pragma("unroll") \
        for (int mi = 0; mi < 4; mi++) { \
            _Pragma("unroll") \
            for (int ni = 0; ni < 4; ni++) { \
                MMA_TF32(acc[mi][ni], ah[mi], bh2[ni]); \
                MMA_TF32(acc[mi][ni], ah[mi], bl2[ni]); \
                MMA_TF32(acc[mi][ni], al_[mi], bh2[ni]); \
            } \
        } \
    } } while (0)

    LOAD_CHUNK(0);
    STORE_CHUNK(0);
    LOAD_CHUNK(KCH);
    __syncthreads();

    for (int c = 0; c < NCHUNK; c++) {
        COMPUTE_STAGE(c & 1);
        if (c + 1 < NCHUNK) {
            __syncthreads();
            STORE_CHUNK((c + 1) & 1);
            if (c + 2 < NCHUNK) LOAD_CHUNK((c + 2) * KCH);
            __syncthreads();
        }
    }
    __syncthreads();

    // Epilogue: regs -> smem T[128][129] (with weight) -> coalesced global.
    const float w = ((bi < 32) != (bj < 32)) ? 0.5f : 1.0f;
    float* T = sm;
    {
        int r0 = wm * 64 + (lane >> 2);
        int c0 = wn * 32 + ((lane & 3) << 1);
        #pragma unroll
        for (int mi = 0; mi < 4; mi++) {
            #pragma unroll
            for (int ni = 0; ni < 4; ni++) {
                int r = r0 + mi * 16;
                int cc = c0 + ni * 8;
                T[r * 129 + cc]           = acc[mi][ni][0] * w;
                T[r * 129 + cc + 1]       = acc[mi][ni][1] * w;
                T[(r + 8) * 129 + cc]     = acc[mi][ni][2] * w;
                T[(r + 8) * 129 + cc + 1] = acc[mi][ni][3] * w;
            }
        }
    }
    __syncthreads();

    const int gi0 = bi * 128;
    const int gj0 = bj * 128;
    {
        int r = t >> 1, half = t & 1;
        const float* src = T + r * 129 + half * 64;
        float* dst = adj + (size_t)(gi0 + r) * N_TOT + gj0 + half * 64;
        #pragma unroll
        for (int c = 0; c < 64; c += 4)
            *(float4*)(dst + c) = make_float4(src[c], src[c+1], src[c+2], src[c+3]);
    }
    if (bi != bj) {
        int col = t >> 1, half = t & 1;
        float* dst = adj + (size_t)(gj0 + col) * N_TOT + gi0 + half * 64;
        #pragma unroll
        for (int i0 = 0; i0 < 64; i0 += 4) {
            int i = half * 64 + i0;
            float4 v = make_float4(T[(i+0)*129 + col], T[(i+1)*129 + col],
                                   T[(i+2)*129 + col], T[(i+3)*129 + col]);
            *(float4*)(dst + i0) = v;
        }
    }
#undef LOAD_CHUNK
#undef STORE_CHUNK
#undef COMPUTE_STAGE
}

// ---------------------------------------------------------------------------
// Kernel 3: per-row top-15 off-diagonal -> threshold + degree.
// ---------------------------------------------------------------------------
__global__ void __launch_bounds__(256) topk_kernel(const float* __restrict__ adj)
{
    const int i    = blockIdx.x;
    const int t    = threadIdx.x;
    const int lane = t & 31, wid = t >> 5;
    const float4* row4 = (const float4*)(adj + (size_t)i * N_TOT);

    __shared__ float cand[256 * 16];
    __shared__ float s_diag;
    __shared__ float warpv[8];
    __shared__ int   warpa[8];
    __shared__ int   s_garg;

    float top[16];
    #pragma unroll
    for (int q = 0; q < 16; q++) top[q] = -INFINITY;

    for (int it = 0; it < 8; it++) {
        int idx4 = t + it * 256;
        float4 v = row4[idx4];
        int j = idx4 * 4;
        float vals[4] = {v.x, v.y, v.z, v.w};
        #pragma unroll
        for (int c = 0; c < 4; c++) {
            float val = vals[c];
            if (j + c == i) { s_diag = val; val = -INFINITY; }
            if (val > top[15]) {
                top[15] = val;
                #pragma unroll
                for (int q = 15; q > 0; q--) {
                    if (top[q] > top[q-1]) {
                        float tmp = top[q-1]; top[q-1] = top[q]; top[q] = tmp;
                    }
                }
            }
        }
    }
    #pragma unroll
    for (int q = 0; q < 16; q++) cand[t * 16 + q] = top[q];
    __syncthreads();

    int head = 0;
    float sum15 = 0.f, thr = 0.f;
    for (int it = 0; it < 15; it++) {
        float bv = cand[t * 16 + head];
        int   bl = lane;
        #pragma unroll
        for (int off = 16; off; off >>= 1) {
            float ov = __shfl_down_sync(0xffffffffu, bv, off);
            int   ol = __shfl_down_sync(0xffffffffu, bl, off);
            if (ov > bv) { bv = ov; bl = ol; }
        }
        if (lane == 0) { warpv[wid] = bv; warpa[wid] = (wid << 5) | bl; }
        __syncthreads();
        if (t == 0) {
            float g = -INFINITY; int ga = 0;
            #pragma unroll
            for (int w = 0; w < 8; w++)
                if (warpv[w] > g) { g = warpv[w]; ga = warpa[w]; }
            s_garg = ga;
            sum15 += g;
            thr = g;
        }
        __syncthreads();
        if (t == s_garg) head++;
    }

    if (t == 0) {
        float deg = s_diag + sum15;
        deg = fmaxf(deg, 1e-12f);
        g_rsd[i] = 1.0f / sqrtf(deg);
        g_thr[i] = thr;
    }
}

// ---------------------------------------------------------------------------
// Kernel 4: in-place sparsify + symmetric normalize.
// ---------------------------------------------------------------------------
__global__ void __launch_bounds__(256) finalize_kernel(float* __restrict__ adj)
{
    size_t idx = (size_t)blockIdx.x * 256 + threadIdx.x;
    int i = (int)(idx >> 11);
    int j = (int)((idx & 2047) << 2);
    float thr = g_thr[i];
    float ri  = g_rsd[i];

    float4* p = (float4*)adj + idx;
    float4 v = *p;
    float s0 = ri * g_rsd[j + 0];
    float s1 = ri * g_rsd[j + 1];
    float s2 = ri * g_rsd[j + 2];
    float s3 = ri * g_rsd[j + 3];
    v.x = ((j + 0 == i) || (v.x >= thr)) ? v.x * s0 : 0.f;
    v.y = ((j + 1 == i) || (v.y >= thr)) ? v.y * s1 : 0.f;
    v.z = ((j + 2 == i) || (v.z >= thr)) ? v.z * s2 : 0.f;
    v.w = ((j + 3 == i) || (v.w >= thr)) ? v.w * s3 : 0.f;
    *p = v;
}

// ---------------------------------------------------------------------------
extern "C" void kernel_launch(void* const* d_in, const int* in_sizes, int n_in,
                              void* d_out, int out_size)
{
    const float* feats   = (const float*)d_in[0];
    const float* coords  = (const float*)d_in[1];
    const float* hfeats  = (const float*)d_in[2];
    const float* hcoords = (const float*)d_in[3];

    float* adj       = (float*)d_out;
    float* out_feats = adj + (size_t)N_TOT * N_TOT;

    static int smem_set = 0;
    if (!smem_set) {
        cudaFuncSetAttribute(gemm_kernel, cudaFuncAttributeMaxDynamicSharedMemorySize, GEMM_SMEM);
        smem_set = 1;
    }

    prep_kernel<<<N_TOT / 8, dim3(32, 8)>>>(feats, coords, hfeats, hcoords, out_feats);
    gemm_kernel<<<dim3(64, 64), 256, GEMM_SMEM>>>(adj);
    topk_kernel<<<N_TOT, 256>>>(adj);
    finalize_kernel<<<(unsigned)((size_t)N_TOT * N_TOT / 4 / 256), 256>>>(adj);
}

// round 4
// speedup vs baseline: 1.1168x; 1.0801x over previous
#include <cuda_runtime.h>
#include <math.h>
#include <stdint.h>

#define N_TOT 8192
#define B_CUR 4096
#define C_DIM 256
#define KU    288
#define TWO_PI 6.283185307179586f
#define SQA 0.97467943f   // sqrt(0.95)
#define SQP 0.22360680f   // sqrt(0.05)

// Scratch
__device__ float g_U[(size_t)N_TOT * KU];
__device__ float g_thr[N_TOT];
__device__ float g_rsd[N_TOT];

// ---------------------------------------------------------------------------
// Helpers
// ---------------------------------------------------------------------------
__device__ __forceinline__ uint32_t smem_u32(const void* p) {
    uint32_t a;
    asm("{ .reg .u64 t; cvta.to.shared.u64 t, %1; cvt.u32.u64 %0, t; }" : "=r"(a) : "l"(p));
    return a;
}

__device__ __forceinline__ float tf32_trunc(float x) {
    uint32_t u;
    asm("cvt.rna.tf32.f32 %0, %1;" : "=r"(u) : "f"(x));
    return __uint_as_float(u);
}

__device__ __forceinline__ void split2(uint32_t raw, uint32_t& hi, uint32_t& lo) {
    float f = __uint_as_float(raw);
    float h = tf32_trunc(f);
    hi = __float_as_uint(h);
    lo = __float_as_uint(tf32_trunc(f - h));
}

#define LDSM_X4(r0, r1, r2, r3, addr) \
    asm volatile("ldmatrix.sync.aligned.m8n8.x4.shared.b16 {%0,%1,%2,%3}, [%4];" \
        : "=r"(r0), "=r"(r1), "=r"(r2), "=r"(r3) : "r"(addr))

#define MMA_TF32(d, a, b) \
    asm volatile("mma.sync.aligned.m16n8k8.row.col.f32.tf32.tf32.f32 " \
        "{%0,%1,%2,%3}, {%4,%5,%6,%7}, {%8,%9}, {%0,%1,%2,%3};" \
        : "+f"((d)[0]), "+f"((d)[1]), "+f"((d)[2]), "+f"((d)[3]) \
        : "r"((a)[0]), "r"((a)[1]), "r"((a)[2]), "r"((a)[3]), \
          "r"((b)[0]), "r"((b)[1]))

#define CP_ASYNC16(saddr, gptr) \
    asm volatile("cp.async.cg.shared.global [%0], [%1], 16;" :: "r"(saddr), "l"(gptr))
#define CP_COMMIT() asm volatile("cp.async.commit_group;")
#define CP_WAIT2()  asm volatile("cp.async.wait_group 2;")

// ---------------------------------------------------------------------------
// Kernel 1: build U rows; copy raw features to output.
// ---------------------------------------------------------------------------
__global__ void __launch_bounds__(256) prep_kernel(
    const float* __restrict__ feats, const float* __restrict__ coords,
    const float* __restrict__ hfeats, const float* __restrict__ hcoords,
    float* __restrict__ out_feats)
{
    int row  = blockIdx.x * 8 + threadIdx.y;
    int lane = threadIdx.x;

    const float* f = (row < B_CUR) ? (feats  + (size_t)row * C_DIM)
                                   : (hfeats + (size_t)(row - B_CUR) * C_DIM);
    const float* c = (row < B_CUR) ? (coords  + (size_t)row * 4)
                                   : (hcoords + (size_t)(row - B_CUR) * 4);

    float4 va = ((const float4*)f)[lane * 2 + 0];
    float4 vb = ((const float4*)f)[lane * 2 + 1];
    float ss = va.x*va.x + va.y*va.y + va.z*va.z + va.w*va.w
             + vb.x*vb.x + vb.y*vb.y + vb.z*vb.z + vb.w*vb.w;
    #pragma unroll
    for (int off = 16; off; off >>= 1) ss += __shfl_xor_sync(0xffffffffu, ss, off);
    float s = SQA / fmaxf(sqrtf(ss), 1e-12f);

    float* urow = g_U + (size_t)row * KU;
    ((float4*)urow)[lane * 2 + 0] = make_float4(va.x*s, va.y*s, va.z*s, va.w*s);
    ((float4*)urow)[lane * 2 + 1] = make_float4(vb.x*s, vb.y*s, vb.z*s, vb.w*s);

    float4* of = (float4*)(out_feats + (size_t)row * C_DIM);
    of[lane * 2 + 0] = va;
    of[lane * 2 + 1] = vb;

    int d      = lane >> 3;
    int rem    = lane & 7;
    int is_cos = rem >> 2;
    int fr     = rem & 3;
    float ang = c[d] * TWO_PI * (float)(1 << fr);
    float sv, cv;
    sincosf(ang, &sv, &cv);
    float pe = is_cos ? cv : sv;
    float ps = pe * pe;
    #pragma unroll
    for (int off = 16; off; off >>= 1) ps += __shfl_xor_sync(0xffffffffu, ps, off);
    urow[256 + lane] = pe * (SQP / fmaxf(sqrtf(ps), 1e-12f));
}

// ---------------------------------------------------------------------------
// Kernel 2: 3xTF32 GEMM via mma.sync.m16n8k8, A = w .* (U U^T).
// 128x128 CTA tile, 8 warps (2x4), warp tile 64x32.
// 4-stage cp.async pipeline of RAW fp32 K-chunks (KCH=16); tf32 hi/lo split
// done in registers after ldmatrix (halves SMEM traffic, 6 LDSM/warp/k8).
// ---------------------------------------------------------------------------
#define KCH     16
#define STR     20
#define STAGE_FLOATS (2 * 128 * STR)       // A + B raw = 5120 floats = 20KB
#define STAGE_BYTES  (STAGE_FLOATS * 4)
#define BOFF_BYTES   (128 * STR * 4)       // B matrix offset inside stage
#define NSTAGE  4
#define GEMM_SMEM (NSTAGE * STAGE_BYTES)   // 81920B (>= 128*129*4 epilogue)
#define NCHUNK (KU / KCH)                  // 18

__global__ void __launch_bounds__(256) gemm_kernel(float* __restrict__ adj)
{
    const int bi = blockIdx.y;
    const int bj = blockIdx.x;
    if (bj < bi) return;

    extern __shared__ float sm[];
    const int t    = threadIdx.x;
    const int lane = t & 31;
    const int wid  = t >> 5;
    const int wm   = wid >> 2;     // 0..1
    const int wn   = wid & 3;      // 0..3

    const float* Abase = g_U + (size_t)bi * 128 * KU;
    const float* Bbase = g_U + (size_t)bj * 128 * KU;

    float acc[4][4][4];
    #pragma unroll
    for (int mi = 0; mi < 4; mi++)
        #pragma unroll
        for (int ni = 0; ni < 4; ni++)
            #pragma unroll
            for (int q = 0; q < 4; q++) acc[mi][ni][q] = 0.f;

    // LDSM per-lane addressing
    const int arow  = lane & 15;
    const int acol4 = (lane >> 4) << 2;
    const int brow  = ((lane & 16) >> 1) + (lane & 7);
    const int bcol4 = (lane & 8) ? 4 : 0;

    const uint32_t smb = smem_u32(sm);
    const int cr  = t >> 2;        // copy row
    const int cc4 = (t & 3) * 4;   // copy col (floats)

#define ISSUE_STAGE(c) do { \
    const int kb = (c) * KCH; \
    const uint32_t sbase = smb + (uint32_t)(((c) & 3) * STAGE_BYTES); \
    _Pragma("unroll") \
    for (int i = 0; i < 2; i++) { \
        int r = cr + i * 64; \
        uint32_t so = (uint32_t)((r * STR + cc4) * 4); \
        CP_ASYNC16(sbase + so,              Abase + (size_t)r * KU + kb + cc4); \
        CP_ASYNC16(sbase + BOFF_BYTES + so, Bbase + (size_t)r * KU + kb + cc4); \
    } } while (0)

#define COMPUTE_STAGE(s) do { \
    const uint32_t base = smb + (uint32_t)((s) * STAGE_BYTES); \
    _Pragma("unroll") \
    for (int k8 = 0; k8 < KCH; k8 += 8) { \
        uint32_t araw[4][4], braw[4][2]; \
        _Pragma("unroll") \
        for (int mi = 0; mi < 4; mi++) { \
            uint32_t ad = base + (uint32_t)(((wm * 64 + mi * 16 + arow) * STR + k8 + acol4) * 4); \
            LDSM_X4(araw[mi][0], araw[mi][1], araw[mi][2], araw[mi][3], ad); \
        } \
        _Pragma("unroll") \
        for (int nb = 0; nb < 2; nb++) { \
            uint32_t bd = base + (uint32_t)BOFF_BYTES + \
                (uint32_t)(((wn * 32 + nb * 16 + brow) * STR + k8 + bcol4) * 4); \
            LDSM_X4(braw[2*nb][0], braw[2*nb][1], braw[2*nb+1][0], braw[2*nb+1][1], bd); \
        } \
        uint32_t bh[4][2], bl[4][2]; \
        _Pragma("unroll") \
        for (int ni = 0; ni < 4; ni++) { \
            split2(braw[ni][0], bh[ni][0], bl[ni][0]); \
            split2(braw[ni][1], bh[ni][1], bl[ni][1]); \
        } \
        _Pragma("unroll") \
        for (int mi = 0; mi < 4; mi++) { \
            uint32_t ah[4], al[4]; \
            _Pragma("unroll") \
            for (int q = 0; q < 4; q++) split2(araw[mi][q], ah[q], al[q]); \
            _Pragma("unroll") \
            for (int ni = 0; ni < 4; ni++) { \
                MMA_TF32(acc[mi][ni], ah, bh[ni]); \
                MMA_TF32(acc[mi][ni], ah, bl[ni]); \
                MMA_TF32(acc[mi][ni], al, bh[ni]); \
            } \
        } \
    } } while (0)

    ISSUE_STAGE(0); CP_COMMIT();
    ISSUE_STAGE(1); CP_COMMIT();
    ISSUE_STAGE(2); CP_COMMIT();

    for (int c = 0; c < NCHUNK; c++) {
        CP_WAIT2();
        __syncthreads();
        if (c + 3 < NCHUNK) ISSUE_STAGE(c + 3);
        CP_COMMIT();
        COMPUTE_STAGE(c & 3);
    }
    __syncthreads();

    // Epilogue: regs -> smem T[128][129] (with weight) -> coalesced global.
    const float w = ((bi < 32) != (bj < 32)) ? 0.5f : 1.0f;
    float* T = sm;
    {
        int r0 = wm * 64 + (lane >> 2);
        int c0 = wn * 32 + ((lane & 3) << 1);
        #pragma unroll
        for (int mi = 0; mi < 4; mi++) {
            #pragma unroll
            for (int ni = 0; ni < 4; ni++) {
                int r = r0 + mi * 16;
                int cc = c0 + ni * 8;
                T[r * 129 + cc]           = acc[mi][ni][0] * w;
                T[r * 129 + cc + 1]       = acc[mi][ni][1] * w;
                T[(r + 8) * 129 + cc]     = acc[mi][ni][2] * w;
                T[(r + 8) * 129 + cc + 1] = acc[mi][ni][3] * w;
            }
        }
    }
    __syncthreads();

    const int gi0 = bi * 128;
    const int gj0 = bj * 128;
    {
        int r = t >> 1, half = t & 1;
        const float* src = T + r * 129 + half * 64;
        float* dst = adj + (size_t)(gi0 + r) * N_TOT + gj0 + half * 64;
        #pragma unroll
        for (int c = 0; c < 64; c += 4)
            *(float4*)(dst + c) = make_float4(src[c], src[c+1], src[c+2], src[c+3]);
    }
    if (bi != bj) {
        int col = t >> 1, half = t & 1;
        float* dst = adj + (size_t)(gj0 + col) * N_TOT + gi0 + half * 64;
        #pragma unroll
        for (int i0 = 0; i0 < 64; i0 += 4) {
            int i = half * 64 + i0;
            float4 v = make_float4(T[(i+0)*129 + col], T[(i+1)*129 + col],
                                   T[(i+2)*129 + col], T[(i+3)*129 + col]);
            *(float4*)(dst + i0) = v;
        }
    }
#undef ISSUE_STAGE
#undef COMPUTE_STAGE
}

// ---------------------------------------------------------------------------
// Kernel 3: per-row top-15 off-diagonal -> threshold + degree.
// ---------------------------------------------------------------------------
__global__ void __launch_bounds__(256) topk_kernel(const float* __restrict__ adj)
{
    const int i    = blockIdx.x;
    const int t    = threadIdx.x;
    const int lane = t & 31, wid = t >> 5;
    const float4* row4 = (const float4*)(adj + (size_t)i * N_TOT);

    __shared__ float cand[256 * 16];
    __shared__ float s_diag;
    __shared__ float warpv[8];
    __shared__ int   warpa[8];
    __shared__ int   s_garg;

    float top[16];
    #pragma unroll
    for (int q = 0; q < 16; q++) top[q] = -INFINITY;

    for (int it = 0; it < 8; it++) {
        int idx4 = t + it * 256;
        float4 v = row4[idx4];
        int j = idx4 * 4;
        float vals[4] = {v.x, v.y, v.z, v.w};
        #pragma unroll
        for (int c = 0; c < 4; c++) {
            float val = vals[c];
            if (j + c == i) { s_diag = val; val = -INFINITY; }
            if (val > top[15]) {
                top[15] = val;
                #pragma unroll
                for (int q = 15; q > 0; q--) {
                    if (top[q] > top[q-1]) {
                        float tmp = top[q-1]; top[q-1] = top[q]; top[q] = tmp;
                    }
                }
            }
        }
    }
    #pragma unroll
    for (int q = 0; q < 16; q++) cand[t * 16 + q] = top[q];
    __syncthreads();

    int head = 0;
    float sum15 = 0.f, thr = 0.f;
    for (int it = 0; it < 15; it++) {
        float bv = cand[t * 16 + head];
        int   bl = lane;
        #pragma unroll
        for (int off = 16; off; off >>= 1) {
            float ov = __shfl_down_sync(0xffffffffu, bv, off);
            int   ol = __shfl_down_sync(0xffffffffu, bl, off);
            if (ov > bv) { bv = ov; bl = ol; }
        }
        if (lane == 0) { warpv[wid] = bv; warpa[wid] = (wid << 5) | bl; }
        __syncthreads();
        if (t == 0) {
            float g = -INFINITY; int ga = 0;
            #pragma unroll
            for (int w = 0; w < 8; w++)
                if (warpv[w] > g) { g = warpv[w]; ga = warpa[w]; }
            s_garg = ga;
            sum15 += g;
            thr = g;
        }
        __syncthreads();
        if (t == s_garg) head++;
    }

    if (t == 0) {
        float deg = s_diag + sum15;
        deg = fmaxf(deg, 1e-12f);
        g_rsd[i] = 1.0f / sqrtf(deg);
        g_thr[i] = thr;
    }
}

// ---------------------------------------------------------------------------
// Kernel 4: in-place sparsify + symmetric normalize.
// ---------------------------------------------------------------------------
__global__ void __launch_bounds__(256) finalize_kernel(float* __restrict__ adj)
{
    size_t idx = (size_t)blockIdx.x * 256 + threadIdx.x;
    int i = (int)(idx >> 11);
    int j = (int)((idx & 2047) << 2);
    float thr = g_thr[i];
    float ri  = g_rsd[i];

    float4* p = (float4*)adj + idx;
    float4 v = *p;
    float s0 = ri * g_rsd[j + 0];
    float s1 = ri * g_rsd[j + 1];
    float s2 = ri * g_rsd[j + 2];
    float s3 = ri * g_rsd[j + 3];
    v.x = ((j + 0 == i) || (v.x >= thr)) ? v.x * s0 : 0.f;
    v.y = ((j + 1 == i) || (v.y >= thr)) ? v.y * s1 : 0.f;
    v.z = ((j + 2 == i) || (v.z >= thr)) ? v.z * s2 : 0.f;
    v.w = ((j + 3 == i) || (v.w >= thr)) ? v.w * s3 : 0.f;
    *p = v;
}

// ---------------------------------------------------------------------------
extern "C" void kernel_launch(void* const* d_in, const int* in_sizes, int n_in,
                              void* d_out, int out_size)
{
    const float* feats   = (const float*)d_in[0];
    const float* coords  = (const float*)d_in[1];
    const float* hfeats  = (const float*)d_in[2];
    const float* hcoords = (const float*)d_in[3];

    float* adj       = (float*)d_out;
    float* out_feats = adj + (size_t)N_TOT * N_TOT;

    static int smem_set = 0;
    if (!smem_set) {
        cudaFuncSetAttribute(gemm_kernel, cudaFuncAttributeMaxDynamicSharedMemorySize, GEMM_SMEM);
        smem_set = 1;
    }

    prep_kernel<<<N_TOT / 8, dim3(32, 8)>>>(feats, coords, hfeats, hcoords, out_feats);
    gemm_kernel<<<dim3(64, 64), 256, GEMM_SMEM>>>(adj);
    topk_kernel<<<N_TOT, 256>>>(adj);
    finalize_kernel<<<(unsigned)((size_t)N_TOT * N_TOT / 4 / 256), 256>>>(adj);
}

// round 5
// speedup vs baseline: 1.3304x; 1.1912x over previous
#include <cuda_runtime.h>
#include <cuda_bf16.h>
#include <math.h>
#include <stdint.h>

#define N_TOT 8192
#define B_CUR 4096
#define C_DIM 256
#define KU    288
#define TWO_PI 6.283185307179586f
#define SQA 0.97467943f   // sqrt(0.95)
#define SQP 0.22360680f   // sqrt(0.05)

// Scratch: bf16 hi/lo split of U (row-major, 288 wide)
__device__ __align__(16) __nv_bfloat16 g_Uh[(size_t)N_TOT * KU];
__device__ __align__(16) __nv_bfloat16 g_Ul[(size_t)N_TOT * KU];
__device__ float g_thr[N_TOT];
__device__ float g_rsd[N_TOT];

// ---------------------------------------------------------------------------
// Helpers
// ---------------------------------------------------------------------------
__device__ __forceinline__ uint32_t smem_u32(const void* p) {
    uint32_t a;
    asm("{ .reg .u64 t; cvta.to.shared.u64 t, %1; cvt.u32.u64 %0, t; }" : "=r"(a) : "l"(p));
    return a;
}

#define LDSM_X4(r0, r1, r2, r3, addr) \
    asm volatile("ldmatrix.sync.aligned.m8n8.x4.shared.b16 {%0,%1,%2,%3}, [%4];" \
        : "=r"(r0), "=r"(r1), "=r"(r2), "=r"(r3) : "r"(addr))

#define MMA_BF16(d, a, b) \
    asm volatile("mma.sync.aligned.m16n8k16.row.col.f32.bf16.bf16.f32 " \
        "{%0,%1,%2,%3}, {%4,%5,%6,%7}, {%8,%9}, {%0,%1,%2,%3};" \
        : "+f"((d)[0]), "+f"((d)[1]), "+f"((d)[2]), "+f"((d)[3]) \
        : "r"((a)[0]), "r"((a)[1]), "r"((a)[2]), "r"((a)[3]), \
          "r"((b)[0]), "r"((b)[1]))

#define CP_ASYNC16(saddr, gptr) \
    asm volatile("cp.async.cg.shared.global [%0], [%1], 16;" :: "r"(saddr), "l"(gptr))
#define CP_COMMIT() asm volatile("cp.async.commit_group;")
#define CP_WAIT2()  asm volatile("cp.async.wait_group 2;")

__device__ __forceinline__ void split_store(float v, __nv_bfloat16* ph, __nv_bfloat16* pl) {
    __nv_bfloat16 h = __float2bfloat16(v);
    *ph = h;
    *pl = __float2bfloat16(v - __bfloat162float(h));
}

// ---------------------------------------------------------------------------
// Kernel 1: build U rows (bf16 hi/lo split), copy raw features to output.
// ---------------------------------------------------------------------------
__global__ void __launch_bounds__(256) prep_kernel(
    const float* __restrict__ feats, const float* __restrict__ coords,
    const float* __restrict__ hfeats, const float* __restrict__ hcoords,
    float* __restrict__ out_feats)
{
    int row  = blockIdx.x * 8 + threadIdx.y;
    int lane = threadIdx.x;

    const float* f = (row < B_CUR) ? (feats  + (size_t)row * C_DIM)
                                   : (hfeats + (size_t)(row - B_CUR) * C_DIM);
    const float* c = (row < B_CUR) ? (coords  + (size_t)row * 4)
                                   : (hcoords + (size_t)(row - B_CUR) * 4);

    float4 va = ((const float4*)f)[lane * 2 + 0];
    float4 vb = ((const float4*)f)[lane * 2 + 1];
    float ss = va.x*va.x + va.y*va.y + va.z*va.z + va.w*va.w
             + vb.x*vb.x + vb.y*vb.y + vb.z*vb.z + vb.w*vb.w;
    #pragma unroll
    for (int off = 16; off; off >>= 1) ss += __shfl_xor_sync(0xffffffffu, ss, off);
    float s = SQA / fmaxf(sqrtf(ss), 1e-12f);

    __nv_bfloat16* uh = g_Uh + (size_t)row * KU;
    __nv_bfloat16* ul = g_Ul + (size_t)row * KU;
    float uv[8] = {va.x*s, va.y*s, va.z*s, va.w*s, vb.x*s, vb.y*s, vb.z*s, vb.w*s};
    #pragma unroll
    for (int q = 0; q < 8; q++)
        split_store(uv[q], uh + lane * 8 + q, ul + lane * 8 + q);

    float4* of = (float4*)(out_feats + (size_t)row * C_DIM);
    of[lane * 2 + 0] = va;
    of[lane * 2 + 1] = vb;

    int d      = lane >> 3;
    int rem    = lane & 7;
    int is_cos = rem >> 2;
    int fr     = rem & 3;
    float ang = c[d] * TWO_PI * (float)(1 << fr);
    float sv, cv;
    sincosf(ang, &sv, &cv);
    float pe = is_cos ? cv : sv;
    float ps = pe * pe;
    #pragma unroll
    for (int off = 16; off; off >>= 1) ps += __shfl_xor_sync(0xffffffffu, ps, off);
    float pv = pe * (SQP / fmaxf(sqrtf(ps), 1e-12f));
    split_store(pv, uh + 256 + lane, ul + 256 + lane);
}

// ---------------------------------------------------------------------------
// Kernel 2: 3-term bf16 GEMM via mma.sync.m16n8k16, A = w .* (U U^T).
// 128x128 CTA tile, 8 warps (2x4), warp tile 64x32. K-chunks of 32,
// 4-stage cp.async of {Ah,Al,Bh,Bl} bf16 tiles. Row stride 80B: 16B-aligned
// and conflict-free for ldmatrix (r*80 mod 128 covers all 8 16B slots).
// ---------------------------------------------------------------------------
#define KCH        32
#define ROW_BYTES  80                       // 32 bf16 = 64B data + 16B pad
#define MAT_BYTES  (128 * ROW_BYTES)        // 10240
#define STAGE_BYTES (4 * MAT_BYTES)         // 40960
#define NSTAGE     4
#define GEMM_SMEM  (NSTAGE * STAGE_BYTES)   // 163840 (>= 128*129*4 epilogue)
#define NCHUNK     (KU / KCH)               // 9
#define ROW_GBYTES (KU * 2)                 // 576 bytes per U row

__global__ void __launch_bounds__(256) gemm_kernel(float* __restrict__ adj)
{
    const int bi = blockIdx.y;
    const int bj = blockIdx.x;
    if (bj < bi) return;

    extern __shared__ float sm[];
    const int t    = threadIdx.x;
    const int lane = t & 31;
    const int wid  = t >> 5;
    const int wm   = wid >> 2;     // 0..1
    const int wn   = wid & 3;      // 0..3

    const char* Ah_g = (const char*)g_Uh + (size_t)bi * 128 * ROW_GBYTES;
    const char* Al_g = (const char*)g_Ul + (size_t)bi * 128 * ROW_GBYTES;
    const char* Bh_g = (const char*)g_Uh + (size_t)bj * 128 * ROW_GBYTES;
    const char* Bl_g = (const char*)g_Ul + (size_t)bj * 128 * ROW_GBYTES;

    float acc[4][4][4];
    #pragma unroll
    for (int mi = 0; mi < 4; mi++)
        #pragma unroll
        for (int ni = 0; ni < 4; ni++)
            #pragma unroll
            for (int q = 0; q < 4; q++) acc[mi][ni][q] = 0.f;

    // LDSM per-lane addressing
    const int arow  = lane & 15;
    const int acolB = (lane >> 4) * 16;                 // 0 or 16 bytes (k 0-7 / 8-15)
    const int brow  = ((lane & 16) >> 1) + (lane & 7);  // +8 rows for hi half
    const int bcolB = (lane & 8) ? 16 : 0;

    const uint32_t smb = smem_u32(sm);

#define ISSUE_STAGE(c) do { \
    const int kbB = (c) * KCH * 2;  /* byte offset of chunk in U row */ \
    const uint32_t sbase = smb + (uint32_t)(((c) & 3) * STAGE_BYTES); \
    _Pragma("unroll") \
    for (int i = 0; i < 2; i++) { \
        int idx = t + (i << 8); \
        int r = idx >> 2; int c16 = (idx & 3) * 16; \
        uint32_t so = (uint32_t)(r * ROW_BYTES + c16); \
        size_t go = (size_t)r * ROW_GBYTES + kbB + c16; \
        CP_ASYNC16(sbase + so,                 Ah_g + go); \
        CP_ASYNC16(sbase + MAT_BYTES + so,     Al_g + go); \
        CP_ASYNC16(sbase + 2 * MAT_BYTES + so, Bh_g + go); \
        CP_ASYNC16(sbase + 3 * MAT_BYTES + so, Bl_g + go); \
    } } while (0)

#define COMPUTE_STAGE(s) do { \
    const uint32_t base = smb + (uint32_t)((s) * STAGE_BYTES); \
    _Pragma("unroll") \
    for (int k16 = 0; k16 < 2; k16++) { \
        const uint32_t kB = (uint32_t)(k16 * 32); \
        uint32_t ah[4][4], al[4][4], bh[4][2], bl[4][2]; \
        _Pragma("unroll") \
        for (int mi = 0; mi < 4; mi++) { \
            uint32_t ad = base + (uint32_t)((wm * 64 + mi * 16 + arow) * ROW_BYTES) + kB + (uint32_t)acolB; \
            LDSM_X4(ah[mi][0], ah[mi][1], ah[mi][2], ah[mi][3], ad); \
            LDSM_X4(al[mi][0], al[mi][1], al[mi][2], al[mi][3], ad + MAT_BYTES); \
        } \
        _Pragma("unroll") \
        for (int nb = 0; nb < 2; nb++) { \
            uint32_t bd = base + (uint32_t)(2 * MAT_BYTES) + \
                (uint32_t)((wn * 32 + nb * 16 + brow) * ROW_BYTES) + kB + (uint32_t)bcolB; \
            LDSM_X4(bh[2*nb][0], bh[2*nb][1], bh[2*nb+1][0], bh[2*nb+1][1], bd); \
            LDSM_X4(bl[2*nb][0], bl[2*nb][1], bl[2*nb+1][0], bl[2*nb+1][1], bd + MAT_BYTES); \
        } \
        _Pragma("unroll") \
        for (int mi = 0; mi < 4; mi++) { \
            _Pragma("unroll") \
            for (int ni = 0; ni < 4; ni++) { \
                MMA_BF16(acc[mi][ni], ah[mi], bh[ni]); \
                MMA_BF16(acc[mi][ni], ah[mi], bl[ni]); \
                MMA_BF16(acc[mi][ni], al[mi], bh[ni]); \
            } \
        } \
    } } while (0)

    ISSUE_STAGE(0); CP_COMMIT();
    ISSUE_STAGE(1); CP_COMMIT();
    ISSUE_STAGE(2); CP_COMMIT();

    for (int c = 0; c < NCHUNK; c++) {
        CP_WAIT2();
        __syncthreads();
        if (c + 3 < NCHUNK) ISSUE_STAGE(c + 3);
        CP_COMMIT();
        COMPUTE_STAGE(c & 3);
    }
    __syncthreads();

    // Epilogue: regs -> smem T[128][129] (with weight) -> coalesced global.
    const float w = ((bi < 32) != (bj < 32)) ? 0.5f : 1.0f;
    float* T = sm;
    {
        int r0 = wm * 64 + (lane >> 2);
        int c0 = wn * 32 + ((lane & 3) << 1);
        #pragma unroll
        for (int mi = 0; mi < 4; mi++) {
            #pragma unroll
            for (int ni = 0; ni < 4; ni++) {
                int r = r0 + mi * 16;
                int cc = c0 + ni * 8;
                T[r * 129 + cc]           = acc[mi][ni][0] * w;
                T[r * 129 + cc + 1]       = acc[mi][ni][1] * w;
                T[(r + 8) * 129 + cc]     = acc[mi][ni][2] * w;
                T[(r + 8) * 129 + cc + 1] = acc[mi][ni][3] * w;
            }
        }
    }
    __syncthreads();

    const int gi0 = bi * 128;
    const int gj0 = bj * 128;
    {
        int r = t >> 1, half = t & 1;
        const float* src = T + r * 129 + half * 64;
        float* dst = adj + (size_t)(gi0 + r) * N_TOT + gj0 + half * 64;
        #pragma unroll
        for (int c = 0; c < 64; c += 4)
            *(float4*)(dst + c) = make_float4(src[c], src[c+1], src[c+2], src[c+3]);
    }
    if (bi != bj) {
        int col = t >> 1, half = t & 1;
        float* dst = adj + (size_t)(gj0 + col) * N_TOT + gi0 + half * 64;
        #pragma unroll
        for (int i0 = 0; i0 < 64; i0 += 4) {
            int i = half * 64 + i0;
            float4 v = make_float4(T[(i+0)*129 + col], T[(i+1)*129 + col],
                                   T[(i+2)*129 + col], T[(i+3)*129 + col]);
            *(float4*)(dst + i0) = v;
        }
    }
#undef ISSUE_STAGE
#undef COMPUTE_STAGE
}

// ---------------------------------------------------------------------------
// Kernel 3: per-row top-15 off-diagonal -> threshold + degree.
// ---------------------------------------------------------------------------
__global__ void __launch_bounds__(256) topk_kernel(const float* __restrict__ adj)
{
    const int i    = blockIdx.x;
    const int t    = threadIdx.x;
    const int lane = t & 31, wid = t >> 5;
    const float4* row4 = (const float4*)(adj + (size_t)i * N_TOT);

    __shared__ float cand[256 * 16];
    __shared__ float s_diag;
    __shared__ float warpv[8];
    __shared__ int   warpa[8];
    __shared__ int   s_garg;

    float top[16];
    #pragma unroll
    for (int q = 0; q < 16; q++) top[q] = -INFINITY;

    for (int it = 0; it < 8; it++) {
        int idx4 = t + it * 256;
        float4 v = row4[idx4];
        int j = idx4 * 4;
        float vals[4] = {v.x, v.y, v.z, v.w};
        #pragma unroll
        for (int c = 0; c < 4; c++) {
            float val = vals[c];
            if (j + c == i) { s_diag = val; val = -INFINITY; }
            if (val > top[15]) {
                top[15] = val;
                #pragma unroll
                for (int q = 15; q > 0; q--) {
                    if (top[q] > top[q-1]) {
                        float tmp = top[q-1]; top[q-1] = top[q]; top[q] = tmp;
                    }
                }
            }
        }
    }
    #pragma unroll
    for (int q = 0; q < 16; q++) cand[t * 16 + q] = top[q];
    __syncthreads();

    int head = 0;
    float sum15 = 0.f, thr = 0.f;
    for (int it = 0; it < 15; it++) {
        float bv = cand[t * 16 + head];
        int   bl = lane;
        #pragma unroll
        for (int off = 16; off; off >>= 1) {
            float ov = __shfl_down_sync(0xffffffffu, bv, off);
            int   ol = __shfl_down_sync(0xffffffffu, bl, off);
            if (ov > bv) { bv = ov; bl = ol; }
        }
        if (lane == 0) { warpv[wid] = bv; warpa[wid] = (wid << 5) | bl; }
        __syncthreads();
        if (t == 0) {
            float g = -INFINITY; int ga = 0;
            #pragma unroll
            for (int w = 0; w < 8; w++)
                if (warpv[w] > g) { g = warpv[w]; ga = warpa[w]; }
            s_garg = ga;
            sum15 += g;
            thr = g;
        }
        __syncthreads();
        if (t == s_garg) head++;
    }

    if (t == 0) {
        float deg = s_diag + sum15;
        deg = fmaxf(deg, 1e-12f);
        g_rsd[i] = 1.0f / sqrtf(deg);
        g_thr[i] = thr;
    }
}

// ---------------------------------------------------------------------------
// Kernel 4: in-place sparsify + symmetric normalize.
// ---------------------------------------------------------------------------
__global__ void __launch_bounds__(256) finalize_kernel(float* __restrict__ adj)
{
    size_t idx = (size_t)blockIdx.x * 256 + threadIdx.x;
    int i = (int)(idx >> 11);
    int j = (int)((idx & 2047) << 2);
    float thr = g_thr[i];
    float ri  = g_rsd[i];

    float4* p = (float4*)adj + idx;
    float4 v = *p;
    float s0 = ri * g_rsd[j + 0];
    float s1 = ri * g_rsd[j + 1];
    float s2 = ri * g_rsd[j + 2];
    float s3 = ri * g_rsd[j + 3];
    v.x = ((j + 0 == i) || (v.x >= thr)) ? v.x * s0 : 0.f;
    v.y = ((j + 1 == i) || (v.y >= thr)) ? v.y * s1 : 0.f;
    v.z = ((j + 2 == i) || (v.z >= thr)) ? v.z * s2 : 0.f;
    v.w = ((j + 3 == i) || (v.w >= thr)) ? v.w * s3 : 0.f;
    *p = v;
}

// ---------------------------------------------------------------------------
extern "C" void kernel_launch(void* const* d_in, const int* in_sizes, int n_in,
                              void* d_out, int out_size)
{
    const float* feats   = (const float*)d_in[0];
    const float* coords  = (const float*)d_in[1];
    const float* hfeats  = (const float*)d_in[2];
    const float* hcoords = (const float*)d_in[3];

    float* adj       = (float*)d_out;
    float* out_feats = adj + (size_t)N_TOT * N_TOT;

    static int smem_set = 0;
    if (!smem_set) {
        cudaFuncSetAttribute(gemm_kernel, cudaFuncAttributeMaxDynamicSharedMemorySize, GEMM_SMEM);
        smem_set = 1;
    }

    prep_kernel<<<N_TOT / 8, dim3(32, 8)>>>(feats, coords, hfeats, hcoords, out_feats);
    gemm_kernel<<<dim3(64, 64), 256, GEMM_SMEM>>>(adj);
    topk_kernel<<<N_TOT, 256>>>(adj);
    finalize_kernel<<<(unsigned)((size_t)N_TOT * N_TOT / 4 / 256), 256>>>(adj);
}